// round 3
// baseline (speedup 1.0000x reference)
#include <cuda_runtime.h>
#include <cstdint>

#define NN 100000
#define NE 3200000
#define NG 64

// ---------------- scratch (static device globals; no allocation) ----------------
__device__ float g_deg[NN];
__device__ float g_dinv[NN];
__device__ float g_norm[NE];
__device__ float g_agg1[NN * 16];
__device__ float g_h1[NN * 16];
__device__ float g_agg2[NN * 16];
__device__ float g_h2[NN * 64];
__device__ float g_agg3[NN * 64];
__device__ float g_sums[NG * 256];
__device__ float g_cnt[NG];

__device__ __forceinline__ float silu(float v) { return v / (1.0f + __expf(-v)); }

__device__ __forceinline__ void redAdd4(float* addr, float a, float b, float c, float d) {
    asm volatile("red.global.add.v4.f32 [%0], {%1,%2,%3,%4};"
                 :: "l"(addr), "f"(a), "f"(b), "f"(c), "f"(d) : "memory");
}

#define FMA2(d, a, b) asm("fma.rn.f32x2 %0, %1, %2, %0;" : "+l"(d) : "l"(a), "l"(b))

// ---------------- init: deg=1, sums=0, cnt=0 ----------------
__global__ void k_init(float* deg, float* sums, float* cnt, int n) {
    int i = blockIdx.x * blockDim.x + threadIdx.x;
    if (i < n) deg[i] = 1.0f;  // self-loop weight
    if (i < NG * 256) sums[i] = 0.f;
    if (i < NG) cnt[i] = 0.f;
}

// deg[dst] += ew, ILP 4
__global__ void k_deg_acc(const int* __restrict__ dst, const float* __restrict__ ew,
                          float* deg, int e) {
    int i0 = (blockIdx.x * blockDim.x + threadIdx.x) * 4;
    if (i0 + 3 < e) {
        int4 d4 = *(const int4*)&dst[i0];
        float4 w4 = *(const float4*)&ew[i0];
        atomicAdd(&deg[d4.x], w4.x);
        atomicAdd(&deg[d4.y], w4.y);
        atomicAdd(&deg[d4.z], w4.z);
        atomicAdd(&deg[d4.w], w4.w);
    } else {
        for (int i = i0; i < e; i++) atomicAdd(&deg[dst[i]], ew[i]);
    }
}

__global__ void k_dinv(const float* __restrict__ deg, float* dinv, int n) {
    int i = blockIdx.x * blockDim.x + threadIdx.x;
    if (i < n) dinv[i] = rsqrtf(deg[i]);
}

// norm = dinv[src]*ew*dinv[dst], ILP 4
__global__ void k_norm(const int* __restrict__ src, const int* __restrict__ dst,
                       const float* __restrict__ ew, const float* __restrict__ dinv,
                       float* __restrict__ norm, int e) {
    int i0 = (blockIdx.x * blockDim.x + threadIdx.x) * 4;
    if (i0 + 3 < e) {
        int4 s4 = *(const int4*)&src[i0];
        int4 d4 = *(const int4*)&dst[i0];
        float4 w4 = *(const float4*)&ew[i0];
        float sa = __ldg(&dinv[s4.x]), sb = __ldg(&dinv[s4.y]),
              sc = __ldg(&dinv[s4.z]), sd = __ldg(&dinv[s4.w]);
        float da = __ldg(&dinv[d4.x]), db = __ldg(&dinv[d4.y]),
              dc = __ldg(&dinv[d4.z]), dd = __ldg(&dinv[d4.w]);
        float4 o;
        o.x = sa * w4.x * da;
        o.y = sb * w4.y * db;
        o.z = sc * w4.z * dc;
        o.w = sd * w4.w * dd;
        *(float4*)&norm[i0] = o;
    } else {
        for (int i = i0; i < e; i++)
            norm[i] = __ldg(&dinv[src[i]]) * ew[i] * __ldg(&dinv[dst[i]]);
    }
}

// warp-aggregated per-graph node count
__global__ void k_cnt(const int* __restrict__ batch, float* cnt, int n) {
    int i = blockIdx.x * blockDim.x + threadIdx.x;
    if (i >= n) return;
    int g = batch[i];
    unsigned act = __activemask();
    unsigned mask = __match_any_sync(act, g);
    int leader = __ffs(mask) - 1;
    if ((threadIdx.x & 31) == leader) atomicAdd(&cnt[g], (float)__popc(mask));
}

// agg1 = x * dinv^2  (self-loop init for layer 1)
__global__ void k_agg1_init(const float* __restrict__ x, const float* __restrict__ dinv,
                            float* agg, int n) {
    int idx = blockIdx.x * blockDim.x + threadIdx.x;  // over n*4 float4
    if (idx >= n * 4) return;
    int node = idx >> 2;
    float d = dinv[node];
    float d2 = d * d;
    float4 v = ((const float4*)x)[idx];
    float4 o = {v.x * d2, v.y * d2, v.z * d2, v.w * d2};
    ((float4*)agg)[idx] = o;
}

// ---------------- edge scatter: agg[dst] += norm * h[src] ----------------
// dim 16: 4 lanes per edge (one float4 each)
__global__ void k_scatter16(const int* __restrict__ src, const int* __restrict__ dst,
                            const float* __restrict__ norm, const float* __restrict__ h,
                            float* agg, int e) {
    int tid = blockIdx.x * blockDim.x + threadIdx.x;
    if (tid >= e * 4) return;
    int ed = tid >> 2;
    int j = tid & 3;
    int s = __ldg(&src[ed]);
    int d = __ldg(&dst[ed]);
    float w = __ldg(&norm[ed]);
    float4 v = ((const float4*)h)[s * 4 + j];
    redAdd4(agg + (size_t)d * 16 + j * 4, v.x * w, v.y * w, v.z * w, v.w * w);
}

// dim 64: 16 lanes per edge
__global__ void k_scatter64(const int* __restrict__ src, const int* __restrict__ dst,
                            const float* __restrict__ norm, const float* __restrict__ h,
                            float* agg, int e) {
    int tid = blockIdx.x * blockDim.x + threadIdx.x;
    if (tid >= e * 16) return;
    int ed = tid >> 4;
    int j = tid & 15;
    int s = __ldg(&src[ed]);
    int d = __ldg(&dst[ed]);
    float w = __ldg(&norm[ed]);
    float4 v = ((const float4*)h)[s * 16 + j];
    redAdd4(agg + (size_t)d * 64 + j * 4, v.x * w, v.y * w, v.z * w, v.w * w);
}

// ---------------- transforms ----------------
// DIN=16, DOUT in {16,64}. h_out = silu(agg@W+b); aggout = h_out*dinv^2 (self-loop seed).
template <int DOUT>
__global__ void k_transform16(const float* __restrict__ agg, const float* __restrict__ W,
                              const float* __restrict__ b, const float* __restrict__ dinv,
                              float* __restrict__ hout, float* __restrict__ aggout, int n) {
    __shared__ float4 sW4[16 * DOUT / 4];
    __shared__ float sB[DOUT];
    int tid = threadIdx.x;
    for (int k = tid; k < 16 * DOUT / 4; k += blockDim.x) sW4[k] = ((const float4*)W)[k];
    for (int k = tid; k < DOUT; k += blockDim.x) sB[k] = b[k];
    __syncthreads();
    int node = blockIdx.x * blockDim.x + tid;
    if (node >= n) return;

    const float4* A4 = (const float4*)(agg + (size_t)node * 16);
    float4 a0 = A4[0], a1 = A4[1], a2 = A4[2], a3 = A4[3];
    float av[16] = {a0.x, a0.y, a0.z, a0.w, a1.x, a1.y, a1.z, a1.w,
                    a2.x, a2.y, a2.z, a2.w, a3.x, a3.y, a3.z, a3.w};

    float4 acc[DOUT / 4];
#pragma unroll
    for (int k = 0; k < DOUT / 4; k++) acc[k] = make_float4(0.f, 0.f, 0.f, 0.f);
#pragma unroll
    for (int i = 0; i < 16; i++) {
#pragma unroll
        for (int k = 0; k < DOUT / 4; k++) {
            float4 w = sW4[i * (DOUT / 4) + k];
            acc[k].x += av[i] * w.x;
            acc[k].y += av[i] * w.y;
            acc[k].z += av[i] * w.z;
            acc[k].w += av[i] * w.w;
        }
    }
    float d = dinv[node];
    float d2 = d * d;
    float4* H4 = (float4*)(hout + (size_t)node * DOUT);
    float4* G4 = (float4*)(aggout + (size_t)node * DOUT);
#pragma unroll
    for (int k = 0; k < DOUT / 4; k++) {
        float4 v;
        v.x = silu(acc[k].x + sB[4 * k + 0]);
        v.y = silu(acc[k].y + sB[4 * k + 1]);
        v.z = silu(acc[k].z + sB[4 * k + 2]);
        v.w = silu(acc[k].w + sB[4 * k + 3]);
        H4[k] = v;
        float4 g = {v.x * d2, v.y * d2, v.z * d2, v.w * d2};
        G4[k] = g;
    }
}

// DIN=64, DOUT=256, fused mean-pool accumulation. 512 threads = 16 warps,
// 4 nodes/warp -> 64 nodes/block. f32x2 packed FMA. smem: W 64KB + A 16KB = 80KB.
__global__ void k_transform64_256_pool(const float* __restrict__ agg,
                                       const float* __restrict__ W,
                                       const float* __restrict__ b,
                                       const int* __restrict__ batch,
                                       float* __restrict__ sums, int n) {
    extern __shared__ float smem[];
    float* sW = smem;             // 64*256
    float* sA = smem + 64 * 256;  // 64*64
    int tid = threadIdx.x;        // 512
    int lane = tid & 31;
    int warp = tid >> 5;
    int nodeBase = blockIdx.x * 64;

    const float4* W4 = (const float4*)W;
    float4* sW4 = (float4*)sW;
#pragma unroll
    for (int k = 0; k < 8; k++) sW4[tid + k * 512] = W4[tid + k * 512];

    const float4* A4 = (const float4*)agg;
    float4* sA4 = (float4*)sA;
    int limit4 = n * 16;  // float4 count of agg
#pragma unroll
    for (int k = 0; k < 2; k++) {
        int gi = nodeBase * 16 + tid + k * 512;
        sA4[tid + k * 512] = (gi < limit4) ? A4[gi] : make_float4(0.f, 0.f, 0.f, 0.f);
    }
    __syncthreads();

    unsigned long long acc[4][4];
#pragma unroll
    for (int j = 0; j < 4; j++)
#pragma unroll
        for (int k = 0; k < 4; k++) acc[j][k] = 0ull;

    int o0 = lane * 8;
#pragma unroll 8
    for (int i = 0; i < 64; i++) {
        ulonglong2 wa = *(const ulonglong2*)&sW[i * 256 + o0];
        ulonglong2 wb = *(const ulonglong2*)&sW[i * 256 + o0 + 4];
#pragma unroll
        for (int j = 0; j < 4; j++) {
            float a = sA[(warp * 4 + j) * 64 + i];
            unsigned long long ap;
            asm("mov.b64 %0, {%1, %1};" : "=l"(ap) : "f"(a));
            FMA2(acc[j][0], ap, wa.x);
            FMA2(acc[j][1], ap, wa.y);
            FMA2(acc[j][2], ap, wb.x);
            FMA2(acc[j][3], ap, wb.y);
        }
    }

    float bb[8];
#pragma unroll
    for (int k = 0; k < 8; k++) bb[k] = __ldg(&b[o0 + k]);

#pragma unroll
    for (int j = 0; j < 4; j++) {
        int node = nodeBase + warp * 4 + j;
        if (node >= n) continue;
        float v[8];
#pragma unroll
        for (int k = 0; k < 4; k++) {
            float lo, hi;
            asm("mov.b64 {%0, %1}, %2;" : "=f"(lo), "=f"(hi) : "l"(acc[j][k]));
            v[2 * k] = lo;
            v[2 * k + 1] = hi;
        }
#pragma unroll
        for (int k = 0; k < 8; k++) v[k] = silu(v[k] + bb[k]);
        int g = __ldg(&batch[node]);
        float* base = sums + (size_t)g * 256 + o0;
        redAdd4(base, v[0], v[1], v[2], v[3]);
        redAdd4(base + 4, v[4], v[5], v[6], v[7]);
    }
}

// ---------------- MLP head: one block per graph ----------------
__global__ void k_mlp(const float* __restrict__ sums, const float* __restrict__ cnt,
                      const float* __restrict__ L1, const float* __restrict__ c1,
                      const float* __restrict__ L2, const float* __restrict__ c2,
                      const float* __restrict__ L3, const float* __restrict__ c3,
                      float* __restrict__ out) {
    __shared__ float sp[256];
    __shared__ float s1[128];
    __shared__ float s2[64];
    int g = blockIdx.x;
    int t = threadIdx.x;  // 128
    float invc = 1.0f / fmaxf(cnt[g], 1.0f);
    sp[t] = sums[g * 256 + t] * invc;
    sp[t + 128] = sums[g * 256 + 128 + t] * invc;
    __syncthreads();
    {
        float acc = c1[t];
        for (int i = 0; i < 256; i++) acc += sp[i] * L1[i * 128 + t];
        s1[t] = silu(acc);
    }
    __syncthreads();
    if (t < 64) {
        float acc = c2[t];
        for (int i = 0; i < 128; i++) acc += s1[i] * L2[i * 64 + t];
        s2[t] = silu(acc);
    }
    __syncthreads();
    if (t < 3) {
        float acc = c3[t];
        for (int i = 0; i < 64; i++) acc += s2[i] * L3[i * 3 + t];
        out[g * 3 + t] = acc;
    }
}

// ---------------- launch ----------------
static void* sym(const void* s) {
    void* p = nullptr;
    cudaGetSymbolAddress(&p, s);
    return p;
}

extern "C" void kernel_launch(void* const* d_in, const int* in_sizes, int n_in,
                              void* d_out, int out_size) {
    const float* x = (const float*)d_in[0];
    const int* ei = (const int*)d_in[1];
    const float* ew = (const float*)d_in[2];
    const int* batch = (const int*)d_in[3];
    const float* W1 = (const float*)d_in[4];
    const float* b1 = (const float*)d_in[5];
    const float* W2 = (const float*)d_in[6];
    const float* b2 = (const float*)d_in[7];
    const float* W3 = (const float*)d_in[8];
    const float* b3 = (const float*)d_in[9];
    const float* L1 = (const float*)d_in[10];
    const float* c1 = (const float*)d_in[11];
    const float* L2 = (const float*)d_in[12];
    const float* c2 = (const float*)d_in[13];
    const float* L3 = (const float*)d_in[14];
    const float* c3 = (const float*)d_in[15];
    float* out = (float*)d_out;

    const int N = in_sizes[0] / 16;  // 100000
    const int E = in_sizes[2];       // 3200000
    const int* src = ei;
    const int* dst = ei + E;

    float* deg = (float*)sym(g_deg);
    float* dinv = (float*)sym(g_dinv);
    float* norm = (float*)sym(g_norm);
    float* agg1 = (float*)sym(g_agg1);
    float* h1 = (float*)sym(g_h1);
    float* agg2 = (float*)sym(g_agg2);
    float* h2 = (float*)sym(g_h2);
    float* agg3 = (float*)sym(g_agg3);
    float* sums = (float*)sym(g_sums);
    float* cnt = (float*)sym(g_cnt);

    const int T = 256;
    int gn = (N + T - 1) / T;
    int ge4 = (E / 4 + T - 1) / T;

    // init + degree + norm (+ independent batch count)
    k_init<<<gn, T>>>(deg, sums, cnt, N);
    k_cnt<<<gn, T>>>(batch, cnt, N);
    k_deg_acc<<<ge4, T>>>(dst, ew, deg, E);
    k_dinv<<<gn, T>>>(deg, dinv, N);
    k_norm<<<ge4, T>>>(src, dst, ew, dinv, norm, E);

    // layer 1 (16 -> 16)
    k_agg1_init<<<(N * 4 + T - 1) / T, T>>>(x, dinv, agg1, N);
    k_scatter16<<<(E * 4 + T - 1) / T, T>>>(src, dst, norm, x, agg1, E);
    k_transform16<16><<<gn, T>>>(agg1, W1, b1, dinv, h1, agg2, N);

    // layer 2 (16 -> 64)
    k_scatter16<<<(E * 4 + T - 1) / T, T>>>(src, dst, norm, h1, agg2, E);
    k_transform16<64><<<gn, T>>>(agg2, W2, b2, dinv, h2, agg3, N);

    // layer 3 (64 -> 256) + fused pool
    k_scatter64<<<(E * 16 + T - 1) / T, T>>>(src, dst, norm, h2, agg3, E);
    {
        int smemBytes = (64 * 256 + 64 * 64) * (int)sizeof(float);  // 80KB
        cudaFuncSetAttribute(k_transform64_256_pool,
                             cudaFuncAttributeMaxDynamicSharedMemorySize, smemBytes);
        int blocks = (N + 63) / 64;
        k_transform64_256_pool<<<blocks, 512, smemBytes>>>(agg3, W3, b3, batch, sums, N);
    }

    // MLP head
    k_mlp<<<NG, 128>>>(sums, cnt, L1, c1, L2, c2, L3, c3, out);
}

// round 4
// speedup vs baseline: 1.3745x; 1.3745x over previous
#include <cuda_runtime.h>
#include <cstdint>

#define NN 100000
#define NE 3200000
#define NG 64

// ---------------- scratch (static device globals; no allocation) ----------------
__device__ float g_deg[NN];
__device__ float g_dinv[NN];
__device__ float g_norm[NE];
__device__ float g_agg1[NN * 16];
__device__ float g_h1[NN * 16];
__device__ float g_agg2[NN * 16];
__device__ float g_h2[NN * 64];
__device__ float g_agg3[NN * 64];
__device__ float g_sums[NG * 256];
__device__ float g_cnt[NG];

__device__ __forceinline__ float silu(float v) { return v / (1.0f + __expf(-v)); }

__device__ __forceinline__ void redAdd4(float* addr, float a, float b, float c, float d) {
    asm volatile("red.global.add.v4.f32 [%0], {%1,%2,%3,%4};"
                 :: "l"(addr), "f"(a), "f"(b), "f"(c), "f"(d) : "memory");
}

#define FMA2(d, a, b) asm("fma.rn.f32x2 %0, %1, %2, %0;" : "+l"(d) : "l"(a), "l"(b))

// ---------------- init: deg=1, sums=0, cnt=0 ----------------
__global__ void k_init(float* deg, float* sums, float* cnt, int n) {
    int i = blockIdx.x * blockDim.x + threadIdx.x;
    if (i < n) deg[i] = 1.0f;  // self-loop weight
    if (i < NG * 256) sums[i] = 0.f;
    if (i < NG) cnt[i] = 0.f;
}

// deg[dst] += ew, ILP 4
__global__ void k_deg_acc(const int* __restrict__ dst, const float* __restrict__ ew,
                          float* deg, int e) {
    int i0 = (blockIdx.x * blockDim.x + threadIdx.x) * 4;
    if (i0 + 3 < e) {
        int4 d4 = *(const int4*)&dst[i0];
        float4 w4 = *(const float4*)&ew[i0];
        atomicAdd(&deg[d4.x], w4.x);
        atomicAdd(&deg[d4.y], w4.y);
        atomicAdd(&deg[d4.z], w4.z);
        atomicAdd(&deg[d4.w], w4.w);
    } else {
        for (int i = i0; i < e; i++) atomicAdd(&deg[dst[i]], ew[i]);
    }
}

__global__ void k_dinv(const float* __restrict__ deg, float* dinv, int n) {
    int i = blockIdx.x * blockDim.x + threadIdx.x;
    if (i < n) dinv[i] = rsqrtf(deg[i]);
}

// norm = dinv[src]*ew*dinv[dst], ILP 4
__global__ void k_norm(const int* __restrict__ src, const int* __restrict__ dst,
                       const float* __restrict__ ew, const float* __restrict__ dinv,
                       float* __restrict__ norm, int e) {
    int i0 = (blockIdx.x * blockDim.x + threadIdx.x) * 4;
    if (i0 + 3 < e) {
        int4 s4 = *(const int4*)&src[i0];
        int4 d4 = *(const int4*)&dst[i0];
        float4 w4 = *(const float4*)&ew[i0];
        float sa = __ldg(&dinv[s4.x]), sb = __ldg(&dinv[s4.y]),
              sc = __ldg(&dinv[s4.z]), sd = __ldg(&dinv[s4.w]);
        float da = __ldg(&dinv[d4.x]), db = __ldg(&dinv[d4.y]),
              dc = __ldg(&dinv[d4.z]), dd = __ldg(&dinv[d4.w]);
        float4 o;
        o.x = sa * w4.x * da;
        o.y = sb * w4.y * db;
        o.z = sc * w4.z * dc;
        o.w = sd * w4.w * dd;
        *(float4*)&norm[i0] = o;
    } else {
        for (int i = i0; i < e; i++)
            norm[i] = __ldg(&dinv[src[i]]) * ew[i] * __ldg(&dinv[dst[i]]);
    }
}

// warp-aggregated per-graph node count
__global__ void k_cnt(const int* __restrict__ batch, float* cnt, int n) {
    int i = blockIdx.x * blockDim.x + threadIdx.x;
    if (i >= n) return;
    int g = batch[i];
    unsigned act = __activemask();
    unsigned mask = __match_any_sync(act, g);
    int leader = __ffs(mask) - 1;
    if ((threadIdx.x & 31) == leader) atomicAdd(&cnt[g], (float)__popc(mask));
}

// agg1 = x * dinv^2  (self-loop init for layer 1)
__global__ void k_agg1_init(const float* __restrict__ x, const float* __restrict__ dinv,
                            float* agg, int n) {
    int idx = blockIdx.x * blockDim.x + threadIdx.x;  // over n*4 float4
    if (idx >= n * 4) return;
    int node = idx >> 2;
    float d = dinv[node];
    float d2 = d * d;
    float4 v = ((const float4*)x)[idx];
    float4 o = {v.x * d2, v.y * d2, v.z * d2, v.w * d2};
    ((float4*)agg)[idx] = o;
}

// ---------------- edge scatter: agg[dst] += norm * h[src] ----------------
// dim 16: 4 lanes per edge (one float4 each)
__global__ void k_scatter16(const int* __restrict__ src, const int* __restrict__ dst,
                            const float* __restrict__ norm, const float* __restrict__ h,
                            float* agg, int e) {
    int tid = blockIdx.x * blockDim.x + threadIdx.x;
    if (tid >= e * 4) return;
    int ed = tid >> 2;
    int j = tid & 3;
    int s = __ldg(&src[ed]);
    int d = __ldg(&dst[ed]);
    float w = __ldg(&norm[ed]);
    float4 v = ((const float4*)h)[s * 4 + j];
    redAdd4(agg + (size_t)d * 16 + j * 4, v.x * w, v.y * w, v.z * w, v.w * w);
}

// dim 64: 16 lanes per edge
__global__ void k_scatter64(const int* __restrict__ src, const int* __restrict__ dst,
                            const float* __restrict__ norm, const float* __restrict__ h,
                            float* agg, int e) {
    int tid = blockIdx.x * blockDim.x + threadIdx.x;
    if (tid >= e * 16) return;
    int ed = tid >> 4;
    int j = tid & 15;
    int s = __ldg(&src[ed]);
    int d = __ldg(&dst[ed]);
    float w = __ldg(&norm[ed]);
    float4 v = ((const float4*)h)[s * 16 + j];
    redAdd4(agg + (size_t)d * 64 + j * 4, v.x * w, v.y * w, v.z * w, v.w * w);
}

// ---------------- transforms ----------------
// DIN=16, DOUT in {16,64}. h_out = silu(agg@W+b); aggout = h_out*dinv^2 (self-loop seed).
template <int DOUT>
__global__ void k_transform16(const float* __restrict__ agg, const float* __restrict__ W,
                              const float* __restrict__ b, const float* __restrict__ dinv,
                              float* __restrict__ hout, float* __restrict__ aggout, int n) {
    __shared__ float4 sW4[16 * DOUT / 4];
    __shared__ float sB[DOUT];
    int tid = threadIdx.x;
    for (int k = tid; k < 16 * DOUT / 4; k += blockDim.x) sW4[k] = ((const float4*)W)[k];
    for (int k = tid; k < DOUT; k += blockDim.x) sB[k] = b[k];
    __syncthreads();
    int node = blockIdx.x * blockDim.x + tid;
    if (node >= n) return;

    const float4* A4 = (const float4*)(agg + (size_t)node * 16);
    float4 a0 = A4[0], a1 = A4[1], a2 = A4[2], a3 = A4[3];
    float av[16] = {a0.x, a0.y, a0.z, a0.w, a1.x, a1.y, a1.z, a1.w,
                    a2.x, a2.y, a2.z, a2.w, a3.x, a3.y, a3.z, a3.w};

    float4 acc[DOUT / 4];
#pragma unroll
    for (int k = 0; k < DOUT / 4; k++) acc[k] = make_float4(0.f, 0.f, 0.f, 0.f);
#pragma unroll
    for (int i = 0; i < 16; i++) {
#pragma unroll
        for (int k = 0; k < DOUT / 4; k++) {
            float4 w = sW4[i * (DOUT / 4) + k];
            acc[k].x += av[i] * w.x;
            acc[k].y += av[i] * w.y;
            acc[k].z += av[i] * w.z;
            acc[k].w += av[i] * w.w;
        }
    }
    float d = dinv[node];
    float d2 = d * d;
    float4* H4 = (float4*)(hout + (size_t)node * DOUT);
    float4* G4 = (float4*)(aggout + (size_t)node * DOUT);
#pragma unroll
    for (int k = 0; k < DOUT / 4; k++) {
        float4 v;
        v.x = silu(acc[k].x + sB[4 * k + 0]);
        v.y = silu(acc[k].y + sB[4 * k + 1]);
        v.z = silu(acc[k].z + sB[4 * k + 2]);
        v.w = silu(acc[k].w + sB[4 * k + 3]);
        H4[k] = v;
        float4 g = {v.x * d2, v.y * d2, v.z * d2, v.w * d2};
        G4[k] = g;
    }
}

// DIN=64, DOUT=256, fused mean-pool with warp-aggregated REDs.
// 256 threads = 8 warps, 4 nodes/warp -> 32 nodes/block (R1 launch config).
// f32x2 packed FMA. smem: W 64KB + A 8KB = 72KB.
__global__ void k_transform64_256_pool(const float* __restrict__ agg,
                                       const float* __restrict__ W,
                                       const float* __restrict__ b,
                                       const int* __restrict__ batch,
                                       float* __restrict__ sums, int n) {
    extern __shared__ float smem[];
    float* sW = smem;             // 64*256
    float* sA = smem + 64 * 256;  // 32*64
    int tid = threadIdx.x;        // 256
    int lane = tid & 31;
    int warp = tid >> 5;
    int nodeBase = blockIdx.x * 32;

    const float4* W4 = (const float4*)W;
    float4* sW4 = (float4*)sW;
#pragma unroll
    for (int k = 0; k < 16; k++) sW4[tid + k * 256] = W4[tid + k * 256];

    const float4* A4 = (const float4*)agg;
    float4* sA4 = (float4*)sA;
    int limit4 = n * 16;
#pragma unroll
    for (int k = 0; k < 2; k++) {
        int gi = nodeBase * 16 + tid + k * 256;
        sA4[tid + k * 256] = (gi < limit4) ? A4[gi] : make_float4(0.f, 0.f, 0.f, 0.f);
    }
    __syncthreads();

    unsigned long long acc[4][4];
#pragma unroll
    for (int j = 0; j < 4; j++)
#pragma unroll
        for (int k = 0; k < 4; k++) acc[j][k] = 0ull;

    int o0 = lane * 8;
#pragma unroll 8
    for (int i = 0; i < 64; i++) {
        ulonglong2 wa = *(const ulonglong2*)&sW[i * 256 + o0];
        ulonglong2 wb = *(const ulonglong2*)&sW[i * 256 + o0 + 4];
#pragma unroll
        for (int j = 0; j < 4; j++) {
            float a = sA[(warp * 4 + j) * 64 + i];
            unsigned long long ap;
            asm("mov.b64 %0, {%1, %1};" : "=l"(ap) : "f"(a));
            FMA2(acc[j][0], ap, wa.x);
            FMA2(acc[j][1], ap, wa.y);
            FMA2(acc[j][2], ap, wb.x);
            FMA2(acc[j][3], ap, wb.y);
        }
    }

    float bb[8];
#pragma unroll
    for (int k = 0; k < 8; k++) bb[k] = __ldg(&b[o0 + k]);

    int node0 = nodeBase + warp * 4;
    // graph ids of this warp's 4 nodes (uniform across lanes)
    int g0 = (node0 + 0 < n) ? __ldg(&batch[node0 + 0]) : -1;
    int g1 = (node0 + 1 < n) ? __ldg(&batch[node0 + 1]) : -1;
    int g2 = (node0 + 2 < n) ? __ldg(&batch[node0 + 2]) : -1;
    int g3 = (node0 + 3 < n) ? __ldg(&batch[node0 + 3]) : -1;

    float v[4][8];
#pragma unroll
    for (int j = 0; j < 4; j++) {
#pragma unroll
        for (int k = 0; k < 4; k++) {
            float lo, hi;
            asm("mov.b64 {%0, %1}, %2;" : "=f"(lo), "=f"(hi) : "l"(acc[j][k]));
            v[j][2 * k] = lo;
            v[j][2 * k + 1] = hi;
        }
#pragma unroll
        for (int k = 0; k < 8; k++) v[j][k] = silu(v[j][k] + bb[k]);
    }

    if (g0 >= 0 && g0 == g1 && g1 == g2 && g2 == g3) {
        // common case: all 4 nodes in same graph -> one RED pair per lane
        float s[8];
#pragma unroll
        for (int k = 0; k < 8; k++) s[k] = v[0][k] + v[1][k] + v[2][k] + v[3][k];
        float* base = sums + (size_t)g0 * 256 + o0;
        redAdd4(base, s[0], s[1], s[2], s[3]);
        redAdd4(base + 4, s[4], s[5], s[6], s[7]);
    } else {
        int gs[4] = {g0, g1, g2, g3};
#pragma unroll
        for (int j = 0; j < 4; j++) {
            if (gs[j] < 0) continue;
            float* base = sums + (size_t)gs[j] * 256 + o0;
            redAdd4(base, v[j][0], v[j][1], v[j][2], v[j][3]);
            redAdd4(base + 4, v[j][4], v[j][5], v[j][6], v[j][7]);
        }
    }
}

// ---------------- MLP head: one block per graph ----------------
__global__ void k_mlp(const float* __restrict__ sums, const float* __restrict__ cnt,
                      const float* __restrict__ L1, const float* __restrict__ c1,
                      const float* __restrict__ L2, const float* __restrict__ c2,
                      const float* __restrict__ L3, const float* __restrict__ c3,
                      float* __restrict__ out) {
    __shared__ float sp[256];
    __shared__ float s1[128];
    __shared__ float s2[64];
    int g = blockIdx.x;
    int t = threadIdx.x;  // 128
    float invc = 1.0f / fmaxf(cnt[g], 1.0f);
    sp[t] = sums[g * 256 + t] * invc;
    sp[t + 128] = sums[g * 256 + 128 + t] * invc;
    __syncthreads();
    {
        float acc = c1[t];
        for (int i = 0; i < 256; i++) acc += sp[i] * L1[i * 128 + t];
        s1[t] = silu(acc);
    }
    __syncthreads();
    if (t < 64) {
        float acc = c2[t];
        for (int i = 0; i < 128; i++) acc += s1[i] * L2[i * 64 + t];
        s2[t] = silu(acc);
    }
    __syncthreads();
    if (t < 3) {
        float acc = c3[t];
        for (int i = 0; i < 64; i++) acc += s2[i] * L3[i * 3 + t];
        out[g * 3 + t] = acc;
    }
}

// ---------------- launch ----------------
static void* sym(const void* s) {
    void* p = nullptr;
    cudaGetSymbolAddress(&p, s);
    return p;
}

extern "C" void kernel_launch(void* const* d_in, const int* in_sizes, int n_in,
                              void* d_out, int out_size) {
    const float* x = (const float*)d_in[0];
    const int* ei = (const int*)d_in[1];
    const float* ew = (const float*)d_in[2];
    const int* batch = (const int*)d_in[3];
    const float* W1 = (const float*)d_in[4];
    const float* b1 = (const float*)d_in[5];
    const float* W2 = (const float*)d_in[6];
    const float* b2 = (const float*)d_in[7];
    const float* W3 = (const float*)d_in[8];
    const float* b3 = (const float*)d_in[9];
    const float* L1 = (const float*)d_in[10];
    const float* c1 = (const float*)d_in[11];
    const float* L2 = (const float*)d_in[12];
    const float* c2 = (const float*)d_in[13];
    const float* L3 = (const float*)d_in[14];
    const float* c3 = (const float*)d_in[15];
    float* out = (float*)d_out;

    const int N = in_sizes[0] / 16;  // 100000
    const int E = in_sizes[2];       // 3200000
    const int* src = ei;
    const int* dst = ei + E;

    float* deg = (float*)sym(g_deg);
    float* dinv = (float*)sym(g_dinv);
    float* norm = (float*)sym(g_norm);
    float* agg1 = (float*)sym(g_agg1);
    float* h1 = (float*)sym(g_h1);
    float* agg2 = (float*)sym(g_agg2);
    float* h2 = (float*)sym(g_h2);
    float* agg3 = (float*)sym(g_agg3);
    float* sums = (float*)sym(g_sums);
    float* cnt = (float*)sym(g_cnt);

    const int T = 256;
    int gn = (N + T - 1) / T;
    int ge4 = (E / 4 + T - 1) / T;

    // init + degree + norm (+ independent batch count)
    k_init<<<gn, T>>>(deg, sums, cnt, N);
    k_cnt<<<gn, T>>>(batch, cnt, N);
    k_deg_acc<<<ge4, T>>>(dst, ew, deg, E);
    k_dinv<<<gn, T>>>(deg, dinv, N);
    k_norm<<<ge4, T>>>(src, dst, ew, dinv, norm, E);

    // layer 1 (16 -> 16)
    k_agg1_init<<<(N * 4 + T - 1) / T, T>>>(x, dinv, agg1, N);
    k_scatter16<<<(E * 4 + T - 1) / T, T>>>(src, dst, norm, x, agg1, E);
    k_transform16<16><<<gn, T>>>(agg1, W1, b1, dinv, h1, agg2, N);

    // layer 2 (16 -> 64)
    k_scatter16<<<(E * 4 + T - 1) / T, T>>>(src, dst, norm, h1, agg2, E);
    k_transform16<64><<<gn, T>>>(agg2, W2, b2, dinv, h2, agg3, N);

    // layer 3 (64 -> 256) + fused pool
    k_scatter64<<<(E * 16 + T - 1) / T, T>>>(src, dst, norm, h2, agg3, E);
    {
        int smemBytes = (64 * 256 + 32 * 64) * (int)sizeof(float);  // 72KB
        cudaFuncSetAttribute(k_transform64_256_pool,
                             cudaFuncAttributeMaxDynamicSharedMemorySize, smemBytes);
        int blocks = (N + 31) / 32;
        k_transform64_256_pool<<<blocks, 256, smemBytes>>>(agg3, W3, b3, batch, sums, N);
    }

    // MLP head
    k_mlp<<<NG, 128>>>(sums, cnt, L1, c1, L2, c2, L3, c3, out);
}

// round 5
// speedup vs baseline: 1.4289x; 1.0396x over previous
#include <cuda_runtime.h>
#include <cuda_fp16.h>
#include <cstdint>

#define NN 100000
#define NE 3200000
#define NG 64

// ---------------- scratch (static device globals; no allocation) ----------------
__device__ float g_deg[NN];
__device__ float g_dinv[NN];
__device__ float g_norm[NE];
__device__ __half g_xh[NN * 16];
__device__ float g_agg1[NN * 16];
__device__ __half g_h1[NN * 16];
__device__ float g_agg2[NN * 16];
__device__ __half g_h2[NN * 64];
__device__ float g_agg3[NN * 64];
__device__ float g_sums[NG * 256];
__device__ float g_cnt[NG];

__device__ __forceinline__ float silu(float v) { return v / (1.0f + __expf(-v)); }

__device__ __forceinline__ void redAdd4(float* addr, float a, float b, float c, float d) {
    asm volatile("red.global.add.v4.f32 [%0], {%1,%2,%3,%4};"
                 :: "l"(addr), "f"(a), "f"(b), "f"(c), "f"(d) : "memory");
}

#define FMA2(d, a, b) asm("fma.rn.f32x2 %0, %1, %2, %0;" : "+l"(d) : "l"(a), "l"(b))

// pack 4 floats -> 4 halves in a uint2
__device__ __forceinline__ uint2 pack4h(float a, float b, float c, float d) {
    __half2 h0 = __floats2half2_rn(a, b);
    __half2 h1 = __floats2half2_rn(c, d);
    uint2 r;
    r.x = *(unsigned*)&h0;
    r.y = *(unsigned*)&h1;
    return r;
}

// ---------------- init: deg=1, sums=0, cnt=0 ----------------
__global__ void k_init(float* deg, float* sums, float* cnt, int n) {
    int i = blockIdx.x * blockDim.x + threadIdx.x;
    if (i < n) deg[i] = 1.0f;  // self-loop weight
    if (i < NG * 256) sums[i] = 0.f;
    if (i < NG) cnt[i] = 0.f;
}

// deg[dst] += ew, ILP 4
__global__ void k_deg_acc(const int* __restrict__ dst, const float* __restrict__ ew,
                          float* deg, int e) {
    int i0 = (blockIdx.x * blockDim.x + threadIdx.x) * 4;
    if (i0 + 3 < e) {
        int4 d4 = *(const int4*)&dst[i0];
        float4 w4 = *(const float4*)&ew[i0];
        atomicAdd(&deg[d4.x], w4.x);
        atomicAdd(&deg[d4.y], w4.y);
        atomicAdd(&deg[d4.z], w4.z);
        atomicAdd(&deg[d4.w], w4.w);
    } else {
        for (int i = i0; i < e; i++) atomicAdd(&deg[dst[i]], ew[i]);
    }
}

__global__ void k_dinv(const float* __restrict__ deg, float* dinv, int n) {
    int i = blockIdx.x * blockDim.x + threadIdx.x;
    if (i < n) dinv[i] = rsqrtf(deg[i]);
}

// norm = dinv[src]*ew*dinv[dst], ILP 4
__global__ void k_norm(const int* __restrict__ src, const int* __restrict__ dst,
                       const float* __restrict__ ew, const float* __restrict__ dinv,
                       float* __restrict__ norm, int e) {
    int i0 = (blockIdx.x * blockDim.x + threadIdx.x) * 4;
    if (i0 + 3 < e) {
        int4 s4 = *(const int4*)&src[i0];
        int4 d4 = *(const int4*)&dst[i0];
        float4 w4 = *(const float4*)&ew[i0];
        float sa = __ldg(&dinv[s4.x]), sb = __ldg(&dinv[s4.y]),
              sc = __ldg(&dinv[s4.z]), sd = __ldg(&dinv[s4.w]);
        float da = __ldg(&dinv[d4.x]), db = __ldg(&dinv[d4.y]),
              dc = __ldg(&dinv[d4.z]), dd = __ldg(&dinv[d4.w]);
        float4 o;
        o.x = sa * w4.x * da;
        o.y = sb * w4.y * db;
        o.z = sc * w4.z * dc;
        o.w = sd * w4.w * dd;
        *(float4*)&norm[i0] = o;
    } else {
        for (int i = i0; i < e; i++)
            norm[i] = __ldg(&dinv[src[i]]) * ew[i] * __ldg(&dinv[dst[i]]);
    }
}

// warp-aggregated per-graph node count
__global__ void k_cnt(const int* __restrict__ batch, float* cnt, int n) {
    int i = blockIdx.x * blockDim.x + threadIdx.x;
    if (i >= n) return;
    int g = batch[i];
    unsigned act = __activemask();
    unsigned mask = __match_any_sync(act, g);
    int leader = __ffs(mask) - 1;
    if ((threadIdx.x & 31) == leader) atomicAdd(&cnt[g], (float)__popc(mask));
}

// agg1 = x * dinv^2 (fp32 self-loop seed) AND xh = fp16(x) for the gather path
__global__ void k_agg1_init(const float* __restrict__ x, const float* __restrict__ dinv,
                            float* agg, __half* xh, int n) {
    int idx = blockIdx.x * blockDim.x + threadIdx.x;  // over n*4 float4
    if (idx >= n * 4) return;
    int node = idx >> 2;
    float d = dinv[node];
    float d2 = d * d;
    float4 v = ((const float4*)x)[idx];
    float4 o = {v.x * d2, v.y * d2, v.z * d2, v.w * d2};
    ((float4*)agg)[idx] = o;
    ((uint2*)xh)[idx] = pack4h(v.x, v.y, v.z, v.w);
}

// ---------------- edge scatter: agg[dst] += norm * h[src] (fp16 gather, fp32 RED) --
// dim 16: 4 lanes per edge, each lane 4 halves in + 16B RED out
__global__ void k_scatter16h(const int* __restrict__ src, const int* __restrict__ dst,
                             const float* __restrict__ norm, const __half* __restrict__ h,
                             float* agg, int e) {
    int tid = blockIdx.x * blockDim.x + threadIdx.x;
    if (tid >= e * 4) return;
    int ed = tid >> 2;
    int j = tid & 3;
    int s = __ldg(&src[ed]);
    int d = __ldg(&dst[ed]);
    float w = __ldg(&norm[ed]);
    uint2 raw = ((const uint2*)h)[s * 4 + j];
    float2 f0 = __half22float2(*(__half2*)&raw.x);
    float2 f1 = __half22float2(*(__half2*)&raw.y);
    redAdd4(agg + (size_t)d * 16 + j * 4, f0.x * w, f0.y * w, f1.x * w, f1.y * w);
}

// dim 64: 16 lanes per edge, each lane 4 halves in + 16B RED out
__global__ void k_scatter64h(const int* __restrict__ src, const int* __restrict__ dst,
                             const float* __restrict__ norm, const __half* __restrict__ h,
                             float* agg, int e) {
    int tid = blockIdx.x * blockDim.x + threadIdx.x;
    if (tid >= e * 16) return;
    int ed = tid >> 4;
    int j = tid & 15;
    int s = __ldg(&src[ed]);
    int d = __ldg(&dst[ed]);
    float w = __ldg(&norm[ed]);
    uint2 raw = ((const uint2*)h)[s * 16 + j];
    float2 f0 = __half22float2(*(__half2*)&raw.x);
    float2 f1 = __half22float2(*(__half2*)&raw.y);
    redAdd4(agg + (size_t)d * 64 + j * 4, f0.x * w, f0.y * w, f1.x * w, f1.y * w);
}

// ---------------- transforms ----------------
// DIN=16, DOUT in {16,64}. h_out(fp16) = silu(agg@W+b); aggout(fp32) = h_out*dinv^2.
template <int DOUT>
__global__ void k_transform16(const float* __restrict__ agg, const float* __restrict__ W,
                              const float* __restrict__ b, const float* __restrict__ dinv,
                              __half* __restrict__ hout, float* __restrict__ aggout, int n) {
    __shared__ float4 sW4[16 * DOUT / 4];
    __shared__ float sB[DOUT];
    int tid = threadIdx.x;
    for (int k = tid; k < 16 * DOUT / 4; k += blockDim.x) sW4[k] = ((const float4*)W)[k];
    for (int k = tid; k < DOUT; k += blockDim.x) sB[k] = b[k];
    __syncthreads();
    int node = blockIdx.x * blockDim.x + tid;
    if (node >= n) return;

    const float4* A4 = (const float4*)(agg + (size_t)node * 16);
    float4 a0 = A4[0], a1 = A4[1], a2 = A4[2], a3 = A4[3];
    float av[16] = {a0.x, a0.y, a0.z, a0.w, a1.x, a1.y, a1.z, a1.w,
                    a2.x, a2.y, a2.z, a2.w, a3.x, a3.y, a3.z, a3.w};

    float4 acc[DOUT / 4];
#pragma unroll
    for (int k = 0; k < DOUT / 4; k++) acc[k] = make_float4(0.f, 0.f, 0.f, 0.f);
#pragma unroll
    for (int i = 0; i < 16; i++) {
#pragma unroll
        for (int k = 0; k < DOUT / 4; k++) {
            float4 w = sW4[i * (DOUT / 4) + k];
            acc[k].x += av[i] * w.x;
            acc[k].y += av[i] * w.y;
            acc[k].z += av[i] * w.z;
            acc[k].w += av[i] * w.w;
        }
    }
    float d = dinv[node];
    float d2 = d * d;
    uint2* H2 = (uint2*)(hout + (size_t)node * DOUT);
    float4* G4 = (float4*)(aggout + (size_t)node * DOUT);
#pragma unroll
    for (int k = 0; k < DOUT / 4; k++) {
        float4 v;
        v.x = silu(acc[k].x + sB[4 * k + 0]);
        v.y = silu(acc[k].y + sB[4 * k + 1]);
        v.z = silu(acc[k].z + sB[4 * k + 2]);
        v.w = silu(acc[k].w + sB[4 * k + 3]);
        H2[k] = pack4h(v.x, v.y, v.z, v.w);
        float4 g = {v.x * d2, v.y * d2, v.z * d2, v.w * d2};
        G4[k] = g;
    }
}

// DIN=64, DOUT=256, fused mean-pool with warp-aggregated REDs.
// 256 threads = 8 warps, 4 nodes/warp -> 32 nodes/block. f32x2 packed FMA. smem 72KB.
__global__ void k_transform64_256_pool(const float* __restrict__ agg,
                                       const float* __restrict__ W,
                                       const float* __restrict__ b,
                                       const int* __restrict__ batch,
                                       float* __restrict__ sums, int n) {
    extern __shared__ float smem[];
    float* sW = smem;             // 64*256
    float* sA = smem + 64 * 256;  // 32*64
    int tid = threadIdx.x;        // 256
    int lane = tid & 31;
    int warp = tid >> 5;
    int nodeBase = blockIdx.x * 32;

    const float4* W4 = (const float4*)W;
    float4* sW4 = (float4*)sW;
#pragma unroll
    for (int k = 0; k < 16; k++) sW4[tid + k * 256] = W4[tid + k * 256];

    const float4* A4 = (const float4*)agg;
    float4* sA4 = (float4*)sA;
    int limit4 = n * 16;
#pragma unroll
    for (int k = 0; k < 2; k++) {
        int gi = nodeBase * 16 + tid + k * 256;
        sA4[tid + k * 256] = (gi < limit4) ? A4[gi] : make_float4(0.f, 0.f, 0.f, 0.f);
    }
    __syncthreads();

    unsigned long long acc[4][4];
#pragma unroll
    for (int j = 0; j < 4; j++)
#pragma unroll
        for (int k = 0; k < 4; k++) acc[j][k] = 0ull;

    int o0 = lane * 8;
#pragma unroll 8
    for (int i = 0; i < 64; i++) {
        ulonglong2 wa = *(const ulonglong2*)&sW[i * 256 + o0];
        ulonglong2 wb = *(const ulonglong2*)&sW[i * 256 + o0 + 4];
#pragma unroll
        for (int j = 0; j < 4; j++) {
            float a = sA[(warp * 4 + j) * 64 + i];
            unsigned long long ap;
            asm("mov.b64 %0, {%1, %1};" : "=l"(ap) : "f"(a));
            FMA2(acc[j][0], ap, wa.x);
            FMA2(acc[j][1], ap, wa.y);
            FMA2(acc[j][2], ap, wb.x);
            FMA2(acc[j][3], ap, wb.y);
        }
    }

    float bb[8];
#pragma unroll
    for (int k = 0; k < 8; k++) bb[k] = __ldg(&b[o0 + k]);

    int node0 = nodeBase + warp * 4;
    int g0 = (node0 + 0 < n) ? __ldg(&batch[node0 + 0]) : -1;
    int g1 = (node0 + 1 < n) ? __ldg(&batch[node0 + 1]) : -1;
    int g2 = (node0 + 2 < n) ? __ldg(&batch[node0 + 2]) : -1;
    int g3 = (node0 + 3 < n) ? __ldg(&batch[node0 + 3]) : -1;

    float v[4][8];
#pragma unroll
    for (int j = 0; j < 4; j++) {
#pragma unroll
        for (int k = 0; k < 4; k++) {
            float lo, hi;
            asm("mov.b64 {%0, %1}, %2;" : "=f"(lo), "=f"(hi) : "l"(acc[j][k]));
            v[j][2 * k] = lo;
            v[j][2 * k + 1] = hi;
        }
#pragma unroll
        for (int k = 0; k < 8; k++) v[j][k] = silu(v[j][k] + bb[k]);
    }

    if (g0 >= 0 && g0 == g1 && g1 == g2 && g2 == g3) {
        float s[8];
#pragma unroll
        for (int k = 0; k < 8; k++) s[k] = v[0][k] + v[1][k] + v[2][k] + v[3][k];
        float* base = sums + (size_t)g0 * 256 + o0;
        redAdd4(base, s[0], s[1], s[2], s[3]);
        redAdd4(base + 4, s[4], s[5], s[6], s[7]);
    } else {
        int gs[4] = {g0, g1, g2, g3};
#pragma unroll
        for (int j = 0; j < 4; j++) {
            if (gs[j] < 0) continue;
            float* base = sums + (size_t)gs[j] * 256 + o0;
            redAdd4(base, v[j][0], v[j][1], v[j][2], v[j][3]);
            redAdd4(base + 4, v[j][4], v[j][5], v[j][6], v[j][7]);
        }
    }
}

// ---------------- MLP head: one block per graph ----------------
__global__ void k_mlp(const float* __restrict__ sums, const float* __restrict__ cnt,
                      const float* __restrict__ L1, const float* __restrict__ c1,
                      const float* __restrict__ L2, const float* __restrict__ c2,
                      const float* __restrict__ L3, const float* __restrict__ c3,
                      float* __restrict__ out) {
    __shared__ float sp[256];
    __shared__ float s1[128];
    __shared__ float s2[64];
    int g = blockIdx.x;
    int t = threadIdx.x;  // 128
    float invc = 1.0f / fmaxf(cnt[g], 1.0f);
    sp[t] = sums[g * 256 + t] * invc;
    sp[t + 128] = sums[g * 256 + 128 + t] * invc;
    __syncthreads();
    {
        float acc = c1[t];
        for (int i = 0; i < 256; i++) acc += sp[i] * L1[i * 128 + t];
        s1[t] = silu(acc);
    }
    __syncthreads();
    if (t < 64) {
        float acc = c2[t];
        for (int i = 0; i < 128; i++) acc += s1[i] * L2[i * 64 + t];
        s2[t] = silu(acc);
    }
    __syncthreads();
    if (t < 3) {
        float acc = c3[t];
        for (int i = 0; i < 64; i++) acc += s2[i] * L3[i * 3 + t];
        out[g * 3 + t] = acc;
    }
}

// ---------------- launch ----------------
static void* sym(const void* s) {
    void* p = nullptr;
    cudaGetSymbolAddress(&p, s);
    return p;
}

extern "C" void kernel_launch(void* const* d_in, const int* in_sizes, int n_in,
                              void* d_out, int out_size) {
    const float* x = (const float*)d_in[0];
    const int* ei = (const int*)d_in[1];
    const float* ew = (const float*)d_in[2];
    const int* batch = (const int*)d_in[3];
    const float* W1 = (const float*)d_in[4];
    const float* b1 = (const float*)d_in[5];
    const float* W2 = (const float*)d_in[6];
    const float* b2 = (const float*)d_in[7];
    const float* W3 = (const float*)d_in[8];
    const float* b3 = (const float*)d_in[9];
    const float* L1 = (const float*)d_in[10];
    const float* c1 = (const float*)d_in[11];
    const float* L2 = (const float*)d_in[12];
    const float* c2 = (const float*)d_in[13];
    const float* L3 = (const float*)d_in[14];
    const float* c3 = (const float*)d_in[15];
    float* out = (float*)d_out;

    const int N = in_sizes[0] / 16;  // 100000
    const int E = in_sizes[2];       // 3200000
    const int* src = ei;
    const int* dst = ei + E;

    float* deg = (float*)sym(g_deg);
    float* dinv = (float*)sym(g_dinv);
    float* norm = (float*)sym(g_norm);
    __half* xh = (__half*)sym(g_xh);
    float* agg1 = (float*)sym(g_agg1);
    __half* h1 = (__half*)sym(g_h1);
    float* agg2 = (float*)sym(g_agg2);
    __half* h2 = (__half*)sym(g_h2);
    float* agg3 = (float*)sym(g_agg3);
    float* sums = (float*)sym(g_sums);
    float* cnt = (float*)sym(g_cnt);

    const int T = 256;
    int gn = (N + T - 1) / T;
    int ge4 = (E / 4 + T - 1) / T;

    // init + degree + norm (+ independent batch count)
    k_init<<<gn, T>>>(deg, sums, cnt, N);
    k_cnt<<<gn, T>>>(batch, cnt, N);
    k_deg_acc<<<ge4, T>>>(dst, ew, deg, E);
    k_dinv<<<gn, T>>>(deg, dinv, N);
    k_norm<<<ge4, T>>>(src, dst, ew, dinv, norm, E);

    // layer 1 (16 -> 16)
    k_agg1_init<<<(N * 4 + T - 1) / T, T>>>(x, dinv, agg1, xh, N);
    k_scatter16h<<<(E * 4 + T - 1) / T, T>>>(src, dst, norm, xh, agg1, E);
    k_transform16<16><<<gn, T>>>(agg1, W1, b1, dinv, h1, agg2, N);

    // layer 2 (16 -> 64)
    k_scatter16h<<<(E * 4 + T - 1) / T, T>>>(src, dst, norm, h1, agg2, E);
    k_transform16<64><<<gn, T>>>(agg2, W2, b2, dinv, h2, agg3, N);

    // layer 3 (64 -> 256) + fused pool
    k_scatter64h<<<(E * 16 + T - 1) / T, T>>>(src, dst, norm, h2, agg3, E);
    {
        int smemBytes = (64 * 256 + 32 * 64) * (int)sizeof(float);  // 72KB
        cudaFuncSetAttribute(k_transform64_256_pool,
                             cudaFuncAttributeMaxDynamicSharedMemorySize, smemBytes);
        int blocks = (N + 31) / 32;
        k_transform64_256_pool<<<blocks, 256, smemBytes>>>(agg3, W3, b3, batch, sums, N);
    }

    // MLP head
    k_mlp<<<NG, 128>>>(sums, cnt, L1, c1, L2, c2, L3, c3, out);
}

// round 6
// speedup vs baseline: 1.5836x; 1.1083x over previous
#include <cuda_runtime.h>
#include <cuda_fp16.h>
#include <cstdint>

#define NN 100000
#define NE 3200000
#define NG 64
#define SCAN_CHUNK 4096
#define NB_SCAN ((NN + SCAN_CHUNK - 1) / SCAN_CHUNK)  // 25

// ---------------- scratch (static device globals; no allocation) ----------------
__device__ float g_dinv[NN];
__device__ int   g_row_ptr[NN + 1];
__device__ int   g_cur[NN];        // histogram, then fill cursor
__device__ int   g_partials[64];
__device__ int   g_sdst[NE];       // dst sorted (grouped)
__device__ float2 g_srec[NE];      // .x = src bits, .y = ew -> norm (in place)
__device__ __half g_xh[NN * 16];
__device__ float g_agg1[NN * 16];
__device__ __half g_h1[NN * 16];
__device__ float g_agg2[NN * 16];
__device__ __half g_h2[NN * 64];
__device__ float g_agg3[NN * 64];
__device__ float g_sums[NG * 256];
__device__ float g_cnt[NG];

__device__ __forceinline__ float silu(float v) { return v / (1.0f + __expf(-v)); }

__device__ __forceinline__ void redAdd4(float* addr, float a, float b, float c, float d) {
    asm volatile("red.global.add.v4.f32 [%0], {%1,%2,%3,%4};"
                 :: "l"(addr), "f"(a), "f"(b), "f"(c), "f"(d) : "memory");
}

#define FMA2(d, a, b) asm("fma.rn.f32x2 %0, %1, %2, %0;" : "+l"(d) : "l"(a), "l"(b))

__device__ __forceinline__ uint2 pack4h(float a, float b, float c, float d) {
    __half2 h0 = __floats2half2_rn(a, b);
    __half2 h1 = __floats2half2_rn(c, d);
    uint2 r;
    r.x = *(unsigned*)&h0;
    r.y = *(unsigned*)&h1;
    return r;
}

// ---------------- init ----------------
__global__ void k_init(int* cur, float* sums, float* cnt, int n) {
    int i = blockIdx.x * blockDim.x + threadIdx.x;
    if (i < n) cur[i] = 0;
    if (i < NG * 256) sums[i] = 0.f;
    if (i < NG) cnt[i] = 0.f;
}

// histogram of dst, ILP 4
__global__ void k_hist(const int* __restrict__ dst, int* cur, int e) {
    int i0 = (blockIdx.x * blockDim.x + threadIdx.x) * 4;
    if (i0 + 3 < e) {
        int4 d4 = *(const int4*)&dst[i0];
        atomicAdd(&cur[d4.x], 1);
        atomicAdd(&cur[d4.y], 1);
        atomicAdd(&cur[d4.z], 1);
        atomicAdd(&cur[d4.w], 1);
    } else {
        for (int i = i0; i < e; i++) atomicAdd(&cur[dst[i]], 1);
    }
}

__global__ void k_scan1(const int* __restrict__ cnt, int* row_ptr, int* partials, int n) {
    __shared__ int sh[1024];
    int t = threadIdx.x;
    int base = blockIdx.x * SCAN_CHUNK + t * 4;
    int v[4];
    int s = 0;
#pragma unroll
    for (int k = 0; k < 4; k++) {
        int i = base + k;
        v[k] = (i < n) ? cnt[i] : 0;
        s += v[k];
    }
    sh[t] = s;
    __syncthreads();
    for (int off = 1; off < 1024; off <<= 1) {
        int x = (t >= off) ? sh[t - off] : 0;
        __syncthreads();
        sh[t] += x;
        __syncthreads();
    }
    int excl = sh[t] - s;
#pragma unroll
    for (int k = 0; k < 4; k++) {
        int i = base + k;
        if (i < n) row_ptr[i] = excl;
        excl += v[k];
    }
    if (t == 1023) partials[blockIdx.x] = sh[1023];
}

__global__ void k_scan2(int* partials, int nb, int* row_ptr, int n, int e) {
    int run = 0;
    for (int b = 0; b < nb; b++) {
        int t = partials[b];
        partials[b] = run;
        run += t;
    }
    row_ptr[n] = e;
}

__global__ void k_scan3(int* row_ptr, int* cur, const int* __restrict__ partials, int n) {
    int i = blockIdx.x * blockDim.x + threadIdx.x;
    if (i >= n) return;
    int r = row_ptr[i] + partials[i / SCAN_CHUNK];
    row_ptr[i] = r;
    cur[i] = r;
}

// scatter-fill sorted edge arrays
__global__ void k_fill(const int* __restrict__ src, const int* __restrict__ dst,
                       const float* __restrict__ ew, int* cur, int* sdst,
                       float2* srec, int e) {
    int i = blockIdx.x * blockDim.x + threadIdx.x;
    if (i >= e) return;
    int d = dst[i];
    int p = atomicAdd(&cur[d], 1);
    sdst[p] = d;
    float2 rec;
    rec.x = __int_as_float(src[i]);
    rec.y = ew[i];
    srec[p] = rec;
}

// dinv = rsqrt(1 + sum ew over row). One warp per node (coalesced over CSR).
__global__ void k_deg(const int* __restrict__ row_ptr, const float2* __restrict__ srec,
                      float* dinv, int n) {
    int w = (blockIdx.x * blockDim.x + threadIdx.x) >> 5;
    int lane = threadIdx.x & 31;
    if (w >= n) return;
    int s = row_ptr[w], eN = row_ptr[w + 1];
    float sum = 0.f;
    for (int e = s + lane; e < eN; e += 32) sum += srec[e].y;
#pragma unroll
    for (int off = 16; off; off >>= 1) sum += __shfl_xor_sync(0xffffffffu, sum, off);
    if (lane == 0) dinv[w] = rsqrtf(1.0f + sum);
}

// srec.y <- dinv[dst]*ew*dinv[src] (in place). One warp per node.
__global__ void k_normize(const int* __restrict__ row_ptr, float2* srec,
                          const float* __restrict__ dinv, int n) {
    int w = (blockIdx.x * blockDim.x + threadIdx.x) >> 5;
    int lane = threadIdx.x & 31;
    if (w >= n) return;
    int s = row_ptr[w], eN = row_ptr[w + 1];
    float dn = __ldg(&dinv[w]);
    for (int e = s + lane; e < eN; e += 32) {
        float2 r = srec[e];
        int sn = __float_as_int(r.x);
        r.y = dn * r.y * __ldg(&dinv[sn]);
        srec[e] = r;
    }
}

// warp-aggregated per-graph node count
__global__ void k_cnt(const int* __restrict__ batch, float* cnt, int n) {
    int i = blockIdx.x * blockDim.x + threadIdx.x;
    if (i >= n) return;
    int g = batch[i];
    unsigned act = __activemask();
    unsigned mask = __match_any_sync(act, g);
    int leader = __ffs(mask) - 1;
    if ((threadIdx.x & 31) == leader) atomicAdd(&cnt[g], (float)__popc(mask));
}

// agg1 = x * dinv^2 (fp32 self-loop seed) AND xh = fp16(x)
__global__ void k_agg1_init(const float* __restrict__ x, const float* __restrict__ dinv,
                            float* agg, __half* xh, int n) {
    int idx = blockIdx.x * blockDim.x + threadIdx.x;  // over n*4 float4
    if (idx >= n * 4) return;
    int node = idx >> 2;
    float d = dinv[node];
    float d2 = d * d;
    float4 v = ((const float4*)x)[idx];
    float4 o = {v.x * d2, v.y * d2, v.z * d2, v.w * d2};
    ((float4*)agg)[idx] = o;
    ((uint2*)xh)[idx] = pack4h(v.x, v.y, v.z, v.w);
}

// ---------------- run-compressed edge scatter over dst-sorted edges ----------------
// EBLK consecutive edges per thread; register accumulation; RED flush on dst change.
#define EBLK 16

// dim 16: 4 feature chunks. tid -> (edge block, chunk)
__global__ void k_scatter16s(const int* __restrict__ sdst, const float2* __restrict__ srec,
                             const __half* __restrict__ h, float* agg, int e) {
    int tid = blockIdx.x * blockDim.x + threadIdx.x;
    int blk = tid >> 2;
    int j = tid & 3;
    int e0 = blk * EBLK;
    if (e0 >= e) return;
    int e1 = min(e0 + EBLK, e);
    float4 acc = make_float4(0.f, 0.f, 0.f, 0.f);
    int cur = __ldg(&sdst[e0]);
    for (int ee = e0; ee < e1; ee++) {
        int d = __ldg(&sdst[ee]);
        if (d != cur) {
            redAdd4(agg + (size_t)cur * 16 + j * 4, acc.x, acc.y, acc.z, acc.w);
            acc = make_float4(0.f, 0.f, 0.f, 0.f);
            cur = d;
        }
        float2 r = __ldg(&srec[ee]);
        int s = __float_as_int(r.x);
        uint2 raw = ((const uint2*)h)[s * 4 + j];
        float2 f0 = __half22float2(*(__half2*)&raw.x);
        float2 f1 = __half22float2(*(__half2*)&raw.y);
        acc.x += r.y * f0.x;
        acc.y += r.y * f0.y;
        acc.z += r.y * f1.x;
        acc.w += r.y * f1.y;
    }
    redAdd4(agg + (size_t)cur * 16 + j * 4, acc.x, acc.y, acc.z, acc.w);
}

// dim 64: 16 feature chunks.
__global__ void k_scatter64s(const int* __restrict__ sdst, const float2* __restrict__ srec,
                             const __half* __restrict__ h, float* agg, int e) {
    int tid = blockIdx.x * blockDim.x + threadIdx.x;
    int blk = tid >> 4;
    int j = tid & 15;
    int e0 = blk * EBLK;
    if (e0 >= e) return;
    int e1 = min(e0 + EBLK, e);
    float4 acc = make_float4(0.f, 0.f, 0.f, 0.f);
    int cur = __ldg(&sdst[e0]);
    for (int ee = e0; ee < e1; ee++) {
        int d = __ldg(&sdst[ee]);
        if (d != cur) {
            redAdd4(agg + (size_t)cur * 64 + j * 4, acc.x, acc.y, acc.z, acc.w);
            acc = make_float4(0.f, 0.f, 0.f, 0.f);
            cur = d;
        }
        float2 r = __ldg(&srec[ee]);
        int s = __float_as_int(r.x);
        uint2 raw = ((const uint2*)h)[s * 16 + j];
        float2 f0 = __half22float2(*(__half2*)&raw.x);
        float2 f1 = __half22float2(*(__half2*)&raw.y);
        acc.x += r.y * f0.x;
        acc.y += r.y * f0.y;
        acc.z += r.y * f1.x;
        acc.w += r.y * f1.y;
    }
    redAdd4(agg + (size_t)cur * 64 + j * 4, acc.x, acc.y, acc.z, acc.w);
}

// ---------------- transforms ----------------
template <int DOUT>
__global__ void k_transform16(const float* __restrict__ agg, const float* __restrict__ W,
                              const float* __restrict__ b, const float* __restrict__ dinv,
                              __half* __restrict__ hout, float* __restrict__ aggout, int n) {
    __shared__ float4 sW4[16 * DOUT / 4];
    __shared__ float sB[DOUT];
    int tid = threadIdx.x;
    for (int k = tid; k < 16 * DOUT / 4; k += blockDim.x) sW4[k] = ((const float4*)W)[k];
    for (int k = tid; k < DOUT; k += blockDim.x) sB[k] = b[k];
    __syncthreads();
    int node = blockIdx.x * blockDim.x + tid;
    if (node >= n) return;

    const float4* A4 = (const float4*)(agg + (size_t)node * 16);
    float4 a0 = A4[0], a1 = A4[1], a2 = A4[2], a3 = A4[3];
    float av[16] = {a0.x, a0.y, a0.z, a0.w, a1.x, a1.y, a1.z, a1.w,
                    a2.x, a2.y, a2.z, a2.w, a3.x, a3.y, a3.z, a3.w};

    float4 acc[DOUT / 4];
#pragma unroll
    for (int k = 0; k < DOUT / 4; k++) acc[k] = make_float4(0.f, 0.f, 0.f, 0.f);
#pragma unroll
    for (int i = 0; i < 16; i++) {
#pragma unroll
        for (int k = 0; k < DOUT / 4; k++) {
            float4 w = sW4[i * (DOUT / 4) + k];
            acc[k].x += av[i] * w.x;
            acc[k].y += av[i] * w.y;
            acc[k].z += av[i] * w.z;
            acc[k].w += av[i] * w.w;
        }
    }
    float d = dinv[node];
    float d2 = d * d;
    uint2* H2 = (uint2*)(hout + (size_t)node * DOUT);
    float4* G4 = (float4*)(aggout + (size_t)node * DOUT);
#pragma unroll
    for (int k = 0; k < DOUT / 4; k++) {
        float4 v;
        v.x = silu(acc[k].x + sB[4 * k + 0]);
        v.y = silu(acc[k].y + sB[4 * k + 1]);
        v.z = silu(acc[k].z + sB[4 * k + 2]);
        v.w = silu(acc[k].w + sB[4 * k + 3]);
        H2[k] = pack4h(v.x, v.y, v.z, v.w);
        float4 g = {v.x * d2, v.y * d2, v.z * d2, v.w * d2};
        G4[k] = g;
    }
}

// DIN=64, DOUT=256, fused mean-pool with warp-aggregated REDs. f32x2 FMA. smem 72KB.
__global__ void k_transform64_256_pool(const float* __restrict__ agg,
                                       const float* __restrict__ W,
                                       const float* __restrict__ b,
                                       const int* __restrict__ batch,
                                       float* __restrict__ sums, int n) {
    extern __shared__ float smem[];
    float* sW = smem;             // 64*256
    float* sA = smem + 64 * 256;  // 32*64
    int tid = threadIdx.x;        // 256
    int lane = tid & 31;
    int warp = tid >> 5;
    int nodeBase = blockIdx.x * 32;

    const float4* W4 = (const float4*)W;
    float4* sW4 = (float4*)sW;
#pragma unroll
    for (int k = 0; k < 16; k++) sW4[tid + k * 256] = W4[tid + k * 256];

    const float4* A4 = (const float4*)agg;
    float4* sA4 = (float4*)sA;
    int limit4 = n * 16;
#pragma unroll
    for (int k = 0; k < 2; k++) {
        int gi = nodeBase * 16 + tid + k * 256;
        sA4[tid + k * 256] = (gi < limit4) ? A4[gi] : make_float4(0.f, 0.f, 0.f, 0.f);
    }
    __syncthreads();

    unsigned long long acc[4][4];
#pragma unroll
    for (int j = 0; j < 4; j++)
#pragma unroll
        for (int k = 0; k < 4; k++) acc[j][k] = 0ull;

    int o0 = lane * 8;
#pragma unroll 8
    for (int i = 0; i < 64; i++) {
        ulonglong2 wa = *(const ulonglong2*)&sW[i * 256 + o0];
        ulonglong2 wb = *(const ulonglong2*)&sW[i * 256 + o0 + 4];
#pragma unroll
        for (int j = 0; j < 4; j++) {
            float a = sA[(warp * 4 + j) * 64 + i];
            unsigned long long ap;
            asm("mov.b64 %0, {%1, %1};" : "=l"(ap) : "f"(a));
            FMA2(acc[j][0], ap, wa.x);
            FMA2(acc[j][1], ap, wa.y);
            FMA2(acc[j][2], ap, wb.x);
            FMA2(acc[j][3], ap, wb.y);
        }
    }

    float bb[8];
#pragma unroll
    for (int k = 0; k < 8; k++) bb[k] = __ldg(&b[o0 + k]);

    int node0 = nodeBase + warp * 4;
    int g0 = (node0 + 0 < n) ? __ldg(&batch[node0 + 0]) : -1;
    int g1 = (node0 + 1 < n) ? __ldg(&batch[node0 + 1]) : -1;
    int g2 = (node0 + 2 < n) ? __ldg(&batch[node0 + 2]) : -1;
    int g3 = (node0 + 3 < n) ? __ldg(&batch[node0 + 3]) : -1;

    float v[4][8];
#pragma unroll
    for (int j = 0; j < 4; j++) {
#pragma unroll
        for (int k = 0; k < 4; k++) {
            float lo, hi;
            asm("mov.b64 {%0, %1}, %2;" : "=f"(lo), "=f"(hi) : "l"(acc[j][k]));
            v[j][2 * k] = lo;
            v[j][2 * k + 1] = hi;
        }
#pragma unroll
        for (int k = 0; k < 8; k++) v[j][k] = silu(v[j][k] + bb[k]);
    }

    if (g0 >= 0 && g0 == g1 && g1 == g2 && g2 == g3) {
        float s[8];
#pragma unroll
        for (int k = 0; k < 8; k++) s[k] = v[0][k] + v[1][k] + v[2][k] + v[3][k];
        float* base = sums + (size_t)g0 * 256 + o0;
        redAdd4(base, s[0], s[1], s[2], s[3]);
        redAdd4(base + 4, s[4], s[5], s[6], s[7]);
    } else {
        int gs[4] = {g0, g1, g2, g3};
#pragma unroll
        for (int j = 0; j < 4; j++) {
            if (gs[j] < 0) continue;
            float* base = sums + (size_t)gs[j] * 256 + o0;
            redAdd4(base, v[j][0], v[j][1], v[j][2], v[j][3]);
            redAdd4(base + 4, v[j][4], v[j][5], v[j][6], v[j][7]);
        }
    }
}

// ---------------- MLP head ----------------
__global__ void k_mlp(const float* __restrict__ sums, const float* __restrict__ cnt,
                      const float* __restrict__ L1, const float* __restrict__ c1,
                      const float* __restrict__ L2, const float* __restrict__ c2,
                      const float* __restrict__ L3, const float* __restrict__ c3,
                      float* __restrict__ out) {
    __shared__ float sp[256];
    __shared__ float s1[128];
    __shared__ float s2[64];
    int g = blockIdx.x;
    int t = threadIdx.x;  // 128
    float invc = 1.0f / fmaxf(cnt[g], 1.0f);
    sp[t] = sums[g * 256 + t] * invc;
    sp[t + 128] = sums[g * 256 + 128 + t] * invc;
    __syncthreads();
    {
        float acc = c1[t];
        for (int i = 0; i < 256; i++) acc += sp[i] * L1[i * 128 + t];
        s1[t] = silu(acc);
    }
    __syncthreads();
    if (t < 64) {
        float acc = c2[t];
        for (int i = 0; i < 128; i++) acc += s1[i] * L2[i * 64 + t];
        s2[t] = silu(acc);
    }
    __syncthreads();
    if (t < 3) {
        float acc = c3[t];
        for (int i = 0; i < 64; i++) acc += s2[i] * L3[i * 3 + t];
        out[g * 3 + t] = acc;
    }
}

// ---------------- launch ----------------
static void* sym(const void* s) {
    void* p = nullptr;
    cudaGetSymbolAddress(&p, s);
    return p;
}

extern "C" void kernel_launch(void* const* d_in, const int* in_sizes, int n_in,
                              void* d_out, int out_size) {
    const float* x = (const float*)d_in[0];
    const int* ei = (const int*)d_in[1];
    const float* ew = (const float*)d_in[2];
    const int* batch = (const int*)d_in[3];
    const float* W1 = (const float*)d_in[4];
    const float* b1 = (const float*)d_in[5];
    const float* W2 = (const float*)d_in[6];
    const float* b2 = (const float*)d_in[7];
    const float* W3 = (const float*)d_in[8];
    const float* b3 = (const float*)d_in[9];
    const float* L1 = (const float*)d_in[10];
    const float* c1 = (const float*)d_in[11];
    const float* L2 = (const float*)d_in[12];
    const float* c2 = (const float*)d_in[13];
    const float* L3 = (const float*)d_in[14];
    const float* c3 = (const float*)d_in[15];
    float* out = (float*)d_out;

    const int N = in_sizes[0] / 16;  // 100000
    const int E = in_sizes[2];       // 3200000
    const int* src = ei;
    const int* dst = ei + E;

    float* dinv = (float*)sym(g_dinv);
    int* row_ptr = (int*)sym(g_row_ptr);
    int* cur = (int*)sym(g_cur);
    int* partials = (int*)sym(g_partials);
    int* sdst = (int*)sym(g_sdst);
    float2* srec = (float2*)sym(g_srec);
    __half* xh = (__half*)sym(g_xh);
    float* agg1 = (float*)sym(g_agg1);
    __half* h1 = (__half*)sym(g_h1);
    float* agg2 = (float*)sym(g_agg2);
    __half* h2 = (__half*)sym(g_h2);
    float* agg3 = (float*)sym(g_agg3);
    float* sums = (float*)sym(g_sums);
    float* cnt = (float*)sym(g_cnt);

    const int T = 256;
    int gn = (N + T - 1) / T;
    int ge = (E + T - 1) / T;
    int ge4 = (E / 4 + T - 1) / T;
    int gw = (N * 32 + T - 1) / T;

    int nblk = (E + EBLK - 1) / EBLK;          // edge blocks of 16
    int gs16 = (nblk * 4 + T - 1) / T;
    int gs64 = (nblk * 16 + T - 1) / T;

    // CSR-order sort (counting sort by dst)
    k_init<<<gn, T>>>(cur, sums, cnt, N);
    k_cnt<<<gn, T>>>(batch, cnt, N);
    k_hist<<<ge4, T>>>(dst, cur, E);
    k_scan1<<<NB_SCAN, 1024>>>(cur, row_ptr, partials, N);
    k_scan2<<<1, 1>>>(partials, NB_SCAN, row_ptr, N, E);
    k_scan3<<<gn, T>>>(row_ptr, cur, partials, N);
    k_fill<<<ge, T>>>(src, dst, ew, cur, sdst, srec, E);

    // degree / norm on sorted edges
    k_deg<<<gw, T>>>(row_ptr, srec, dinv, N);
    k_normize<<<gw, T>>>(row_ptr, srec, dinv, N);

    // layer 1 (16 -> 16)
    k_agg1_init<<<(N * 4 + T - 1) / T, T>>>(x, dinv, agg1, xh, N);
    k_scatter16s<<<gs16, T>>>(sdst, srec, xh, agg1, E);
    k_transform16<16><<<gn, T>>>(agg1, W1, b1, dinv, h1, agg2, N);

    // layer 2 (16 -> 64)
    k_scatter16s<<<gs16, T>>>(sdst, srec, h1, agg2, E);
    k_transform16<64><<<gn, T>>>(agg2, W2, b2, dinv, h2, agg3, N);

    // layer 3 (64 -> 256) + fused pool
    k_scatter64s<<<gs64, T>>>(sdst, srec, h2, agg3, E);
    {
        int smemBytes = (64 * 256 + 32 * 64) * (int)sizeof(float);  // 72KB
        cudaFuncSetAttribute(k_transform64_256_pool,
                             cudaFuncAttributeMaxDynamicSharedMemorySize, smemBytes);
        int blocks = (N + 31) / 32;
        k_transform64_256_pool<<<blocks, 256, smemBytes>>>(agg3, W3, b3, batch, sums, N);
    }

    // MLP head
    k_mlp<<<NG, 128>>>(sums, cnt, L1, c1, L2, c2, L3, c3, out);
}